// round 4
// baseline (speedup 1.0000x reference)
#include <cuda_runtime.h>
#include <math.h>

// Geometry (fixed by reference).
#define D_TOTAL 16384
#define H0      4096
#define BATCH   8

// Symmetric block-tridiagonal W: 3 unique 4096x4096 blocks, each applied
// normally (cols) and transposed (rows).
#define TR 256            // tile rows per CTA
#define TC 512            // tile cols per CTA
#define SR 32             // slice rows staged per cp.async round
#define NSLICE (TR / SR)  // 8
#define PITCH 516         // padded floats per smem W/rho row (bank-conflict-free)
#define THREADS 256

// Dynamic smem layout (floats):
//   sW   : 2 * SR * PITCH      = 33024   (double-buffered W slice)
//   rhoN : TR * 16             = 4096    (rho over tile rows, batch-duplicated)
//   rhoT : 8 * PITCH           = 4128    (rho over tile cols, [b][c])
#define SMEM_FLOATS (2 * SR * PITCH + TR * 16 + 8 * PITCH)
#define SMEM_BYTES  (SMEM_FLOATS * 4)

// Exclusive-writer split partials (deterministic, no atomics).
__device__ float g_pn[3][16][BATCH][4096];  // normal: reduced over 16 k-tiles
__device__ float g_pt[3][8][BATCH][4096];   // transpose: reduced over 8 col-tiles

__constant__ int c_brow[3] = {0, 4096, 8192};       // unique block row origins
__constant__ int c_bcol[3] = {4096, 8192, 12288};   // unique block col origins

__device__ __forceinline__ float sigmoid4(float x) {
    return 1.0f / (1.0f + __expf(-4.0f * (x - 0.5f)));
}

typedef unsigned long long u64;

__device__ __forceinline__ u64 ffma2(u64 a, u64 b, u64 c) {
    u64 d;
    asm("fma.rn.f32x2 %0, %1, %2, %3;" : "=l"(d) : "l"(a), "l"(b), "l"(c));
    return d;
}
__device__ __forceinline__ float2 u2f(u64 v) {
    float2 f;
    asm("mov.b64 {%0, %1}, %2;" : "=f"(f.x), "=f"(f.y) : "l"(v));
    return f;
}
__device__ __forceinline__ void cp16(float* sdst, const float* gsrc) {
    unsigned sa = (unsigned)__cvta_generic_to_shared(sdst);
    asm volatile("cp.async.cg.shared.global [%0], [%1], 16;\n" :: "r"(sa), "l"(gsrc));
}
__device__ __forceinline__ void cp_commit() {
    asm volatile("cp.async.commit_group;\n" ::: "memory");
}

// Stage slice s of the CTA tile into buffer (s&1). 16 x 16B per thread, coalesced.
__device__ __forceinline__ void stage_slice(float* sW, const float* gW,
                                            int s, int tid) {
    float* buf = sW + (s & 1) * (SR * PITCH);
    const float* gbase = gW + (size_t)(s * SR) * D_TOTAL;
#pragma unroll
    for (int k = 0; k < 16; k++) {
        int o = tid + THREADS * k;      // 0..4095
        int row = o >> 7;               // 0..31
        int cop = o & 127;              // 16B unit within 512-col row
        cp16(buf + row * PITCH + cop * 4, gbase + (size_t)row * D_TOTAL + cop * 4);
    }
    cp_commit();
}

__global__ void __launch_bounds__(THREADS, 1)
gemv_sym(const float* __restrict__ W, const float* __restrict__ sv) {
    extern __shared__ float smem[];
    float* sW   = smem;
    float* rhoN = smem + 2 * SR * PITCH;
    float* rhoT = rhoN + TR * 16;

    int tid = threadIdx.x;
    int bx  = blockIdx.x;          // 0..383
    int blk = bx >> 7;             // unique block 0..2
    int r   = bx & 127;
    int kt  = r >> 3;              // k-tile 0..15
    int ct  = r & 7;               // col-tile 0..7

    int grow0 = c_brow[blk] + kt * TR;
    int gcol0 = c_bcol[blk] + ct * TC;
    const float* gW = W + (size_t)grow0 * D_TOTAL + gcol0;

    // Kick off DRAM immediately.
    stage_slice(sW, gW, 0, tid);

    // Stage rhoN: thread t owns tile row t. Duplicated pairs for f32x2 operands.
    {
        float v[BATCH];
#pragma unroll
        for (int b = 0; b < BATCH; b++)
            v[b] = sigmoid4(sv[b * D_TOTAL + grow0 + tid]);
        float4* dst = reinterpret_cast<float4*>(rhoN + tid * 16);
        dst[0] = make_float4(v[0], v[0], v[1], v[1]);
        dst[1] = make_float4(v[2], v[2], v[3], v[3]);
        dst[2] = make_float4(v[4], v[4], v[5], v[5]);
        dst[3] = make_float4(v[6], v[6], v[7], v[7]);
    }
    // Stage rhoT[b][c] over the CTA's 512 columns.
    {
        int b = tid >> 5, j = tid & 31;          // 16 cols per thread
        const float4* src = reinterpret_cast<const float4*>(
            sv + b * D_TOTAL + gcol0 + 16 * j);
        float4* dst = reinterpret_cast<float4*>(rhoT + b * PITCH + 16 * j);
#pragma unroll
        for (int q = 0; q < 4; q++) {
            float4 x = src[q];
            dst[q] = make_float4(sigmoid4(x.x), sigmoid4(x.y),
                                 sigmoid4(x.z), sigmoid4(x.w));
        }
    }

    // Normal-pass accumulators: thread = (cg: 4 cols, bg: half of batches).
    int cg = tid & 127, bg = tid >> 7;
    u64 accN[4][2];
#pragma unroll
    for (int i = 0; i < 4; i++) { accN[i][0] = 0ull; accN[i][1] = 0ull; }

    // Transpose-pass identity: thread = (slice row, batch).
    int r32 = tid >> 3, b8 = tid & 7;

#pragma unroll 1
    for (int s = 0; s < NSLICE; s++) {
        if (s + 1 < NSLICE) {
            stage_slice(sW, gW, s + 1, tid);
            asm volatile("cp.async.wait_group 1;\n" ::: "memory");
        } else {
            asm volatile("cp.async.wait_group 0;\n" ::: "memory");
        }
        __syncthreads();

        const float* buf = sW + (s & 1) * (SR * PITCH);

        // ---- Pass A: normal (out cols = W cols) ----
        {
            const float* rbase = rhoN + (s * SR) * 16 + 8 * bg;
#pragma unroll 4
            for (int rr = 0; rr < SR; rr++) {
                ulonglong2 w = *reinterpret_cast<const ulonglong2*>(
                    buf + rr * PITCH + 4 * cg);
                ulonglong2 ra = *reinterpret_cast<const ulonglong2*>(rbase + rr * 16);
                ulonglong2 rb = *reinterpret_cast<const ulonglong2*>(rbase + rr * 16 + 4);
                accN[0][0] = ffma2(w.x, ra.x, accN[0][0]);
                accN[0][1] = ffma2(w.y, ra.x, accN[0][1]);
                accN[1][0] = ffma2(w.x, ra.y, accN[1][0]);
                accN[1][1] = ffma2(w.y, ra.y, accN[1][1]);
                accN[2][0] = ffma2(w.x, rb.x, accN[2][0]);
                accN[2][1] = ffma2(w.y, rb.x, accN[2][1]);
                accN[3][0] = ffma2(w.x, rb.y, accN[3][0]);
                accN[3][1] = ffma2(w.y, rb.y, accN[3][1]);
            }
        }

        // ---- Pass B: transpose (out cols = W rows), per-slice final ----
        {
            const float* wr = buf + r32 * PITCH;
            const float* rr = rhoT + b8 * PITCH;
            u64 a0 = 0ull, a1 = 0ull;
#pragma unroll 8
            for (int c = 0; c < TC; c += 8) {
                ulonglong2 w01 = *reinterpret_cast<const ulonglong2*>(wr + c);
                ulonglong2 w45 = *reinterpret_cast<const ulonglong2*>(wr + c + 4);
                ulonglong2 r01 = *reinterpret_cast<const ulonglong2*>(rr + c);
                ulonglong2 r45 = *reinterpret_cast<const ulonglong2*>(rr + c + 4);
                a0 = ffma2(w01.x, r01.x, a0);
                a1 = ffma2(w01.y, r01.y, a1);
                a0 = ffma2(w45.x, r45.x, a0);
                a1 = ffma2(w45.y, r45.y, a1);
            }
            float2 f0 = u2f(a0), f1 = u2f(a1);
            g_pt[blk][ct][b8][kt * TR + s * SR + r32] = (f0.x + f0.y) + (f1.x + f1.y);
        }
        __syncthreads();   // slice buffer free for reuse
    }

    // Normal partial store: per batch, float4 of this thread's 4 columns.
#pragma unroll
    for (int i = 0; i < 4; i++) {
        float2 c01 = u2f(accN[i][0]);
        float2 c23 = u2f(accN[i][1]);
        *reinterpret_cast<float4*>(&g_pn[blk][kt][bg * 4 + i][ct * TC + 4 * cg]) =
            make_float4(c01.x, c01.y, c23.x, c23.y);
    }
}

// Reduce partials + bias + input drive + rho' gate.
__global__ void finalize_kernel(const float* __restrict__ Ux,
                                const float* __restrict__ sv,
                                const float* __restrict__ bias,
                                float* __restrict__ out) {
    int tid = blockIdx.x * blockDim.x + threadIdx.x;   // 0 .. 131071
    int b  = tid >> 14;
    int d  = tid & (D_TOTAL - 1);
    int cb = d >> 12;
    int dl = d & 4095;

    float a = 0.0f;
    if (cb == 0) {
#pragma unroll
        for (int t = 0; t < 8; t++)  a += g_pt[0][t][b][dl];
    } else if (cb == 1) {
#pragma unroll
        for (int t = 0; t < 16; t++) a += g_pn[0][t][b][dl];
#pragma unroll
        for (int t = 0; t < 8; t++)  a += g_pt[1][t][b][dl];
    } else if (cb == 2) {
#pragma unroll
        for (int t = 0; t < 16; t++) a += g_pn[1][t][b][dl];
#pragma unroll
        for (int t = 0; t < 8; t++)  a += g_pt[2][t][b][dl];
    } else {
#pragma unroll
        for (int t = 0; t < 16; t++) a += g_pn[2][t][b][dl];
    }

    a += bias[d];
    if (d < H0) a += Ux[b * H0 + d];
    float rr = sigmoid4(sv[tid]);
    out[tid] = a * (4.0f * rr * (1.0f - rr));
}

extern "C" void kernel_launch(void* const* d_in, const int* in_sizes, int n_in,
                              void* d_out, int out_size) {
    const float* Ux   = (const float*)d_in[0];   // [8, 4096]
    const float* sv   = (const float*)d_in[1];   // [8, 16384]
    const float* W    = (const float*)d_in[2];   // [16384, 16384]
    const float* bias = (const float*)d_in[3];   // [1, 16384]
    float* out = (float*)d_out;                  // [8, 16384] fp32

    cudaFuncSetAttribute(gemv_sym, cudaFuncAttributeMaxDynamicSharedMemorySize,
                         SMEM_BYTES);

    gemv_sym<<<3 * 16 * 8, THREADS, SMEM_BYTES>>>(W, sv);
    finalize_kernel<<<(BATCH * D_TOTAL) / 256, 256>>>(Ux, sv, bias, out);
}